// round 14
// baseline (speedup 1.0000x reference)
#include <cuda_runtime.h>
#include <cuda.h>
#include <math.h>
#include <stdint.h>

// Problem constants (fixed by the dataset)
#define BATCH   16384
#define NMOD    256
#define NGENE   50
#define NHID    8
#define NCOMP   70

// ---------------- Kernel 1 (TMA, scalar, R9-proven) ----------------
#define T1      256          // threads (8 warps)
#define TROW    256          // batch rows per tile (TMA box dim1)
#define XS      52           // floats per smem row = TMA box dim0 (208B = 13*16)
#define NT      8            // tiles per block
#define TILE_BYTES (TROW * XS * 4)   // 53248

// ---------------- Kernel 1 fallback (cp.async, scalar) ----------------
#define T1F      256
#define SUBB     64
#define NSUB     4
#define WBATCH   (SUBB*NSUB)
#define BLKB     (8*WBATCH)   // 2048
#define FXS      50

// ---------------- Kernel 2 (T2=512, 32 warps/SM) ----------------
#define BT2     32
#define T2      512
#define CPAD    72
#define MS2     33
#define CS2     73           // out_c staging row stride (odd)

// Scratch: m transposed [M][B] (kernel1 writes / kernel2 reads coalesced)
__device__ float g_mT[(size_t)NMOD * BATCH];

// ---------------------------------------------------------------------------
// PTX helpers
// ---------------------------------------------------------------------------
__device__ __forceinline__ void mbar_init(uint32_t mbar, uint32_t cnt) {
    asm volatile("mbarrier.init.shared.b64 [%0], %1;" :: "r"(mbar), "r"(cnt) : "memory");
}
__device__ __forceinline__ void mbar_expect_tx(uint32_t mbar, uint32_t bytes) {
    asm volatile("mbarrier.arrive.expect_tx.shared.b64 _, [%0], %1;"
                 :: "r"(mbar), "r"(bytes) : "memory");
}
__device__ __forceinline__ void mbar_wait(uint32_t mbar, uint32_t parity) {
    asm volatile(
        "{\n\t.reg .pred P1;\n\t"
        "W_%=:\n\t"
        "mbarrier.try_wait.parity.acquire.cta.shared::cta.b64 P1, [%0], %1, 0x989680;\n\t"
        "@P1 bra.uni D_%=;\n\t"
        "bra.uni W_%=;\n\t"
        "D_%=:\n\t}"
        :: "r"(mbar), "r"(parity) : "memory");
}
__device__ __forceinline__ void tma_2d(uint32_t dst, const CUtensorMap* tmap,
                                       int c0, int c1, uint32_t mbar) {
    asm volatile(
        "cp.async.bulk.tensor.2d.shared::cta.global.tile.mbarrier::complete_tx::bytes "
        "[%0], [%1, {%2, %3}], [%4];"
        :: "r"(dst), "l"(tmap), "r"(c0), "r"(c1), "r"(mbar) : "memory");
}
__device__ __forceinline__ void cp_async8(uint32_t dst, const float* src) {
    asm volatile("cp.async.ca.shared.global [%0], [%1], 8;\n" :: "r"(dst), "l"(src));
}
__device__ __forceinline__ void cp_commit() {
    asm volatile("cp.async.commit_group;\n" ::: "memory");
}
template <int N>
__device__ __forceinline__ void cp_wait() {
    asm volatile("cp.async.wait_group %0;\n" :: "n"(N) : "memory");
}

// ---------------------------------------------------------------------------
// Branch-free, MUFU-free tanhshrink (R9-proven): x - tanh(x) = x*C(x^2)/B(x^2)
// ---------------------------------------------------------------------------
__device__ __forceinline__ float tanhshrink_fast(float x) {
    float xc = fminf(fmaxf(x, -7.90531f), 7.90531f);
    float u  = xc * xc;
    float C  = fmaf(u, 2.76076847742355e-16f, -2.00018790482477e-13f);
    C = fmaf(u, C, 8.60467152213735e-11f);
    C = fmaf(u, C, 1.14703542376332e-06f);
    C = fmaf(u, C, 1.03677482114856e-04f);
    C = fmaf(u, C, 1.63117270356356e-03f);
    C = fmaf(u, C, 6.26625990e-10f);
    float B  = fmaf(u, 1.19825839466702e-06f, 1.18534705686654e-04f);
    B = fmaf(u, B, 2.26843463243900e-03f);
    B = fmaf(u, B, 4.89352518554385e-03f);
    float r = __uint_as_float(0x7EF311C3u - __float_as_uint(B));
    r = r * (2.0f - B * r);
    r = r * (2.0f - B * r);
    r = r * (2.0f - B * r);
    return (x - xc) + xc * C * r;
}

// ---------------------------------------------------------------------------
// Core math: per-lane 50x8 MLP + tanhshrink, weights broadcast from smem.
// ---------------------------------------------------------------------------
__device__ __forceinline__ float module_mlp(const float* __restrict__ row,
                                            const float* __restrict__ W1s,
                                            const float* __restrict__ W2s,
                                            float b2v)
{
    float h[NHID];
    #pragma unroll
    for (int j = 0; j < NHID; j++) h[j] = 0.f;

    #pragma unroll 5
    for (int gp = 0; gp < NGENE / 2; gp++) {
        const int g = gp * 2;
        float2 a = *reinterpret_cast<const float2*>(row + g);           // LDS.64
        float4 wa = *reinterpret_cast<const float4*>(W1s + g * 8);      // uniform
        float4 wb = *reinterpret_cast<const float4*>(W1s + g * 8 + 4);
        float4 wc = *reinterpret_cast<const float4*>(W1s + g * 8 + 8);
        float4 wd = *reinterpret_cast<const float4*>(W1s + g * 8 + 12);
        h[0] = fmaf(a.x, wa.x, h[0]); h[1] = fmaf(a.x, wa.y, h[1]);
        h[2] = fmaf(a.x, wa.z, h[2]); h[3] = fmaf(a.x, wa.w, h[3]);
        h[4] = fmaf(a.x, wb.x, h[4]); h[5] = fmaf(a.x, wb.y, h[5]);
        h[6] = fmaf(a.x, wb.z, h[6]); h[7] = fmaf(a.x, wb.w, h[7]);
        h[0] = fmaf(a.y, wc.x, h[0]); h[1] = fmaf(a.y, wc.y, h[1]);
        h[2] = fmaf(a.y, wc.z, h[2]); h[3] = fmaf(a.y, wc.w, h[3]);
        h[4] = fmaf(a.y, wd.x, h[4]); h[5] = fmaf(a.y, wd.y, h[5]);
        h[6] = fmaf(a.y, wd.z, h[6]); h[7] = fmaf(a.y, wd.w, h[7]);
    }
    float acc = b2v;
    #pragma unroll
    for (int j = 0; j < NHID; j++)
        acc = fmaf(tanhshrink_fast(h[j]), W2s[j], acc);
    return tanhshrink_fast(acc);
}

// ---------------------------------------------------------------------------
// Kernel 1 (TMA, R9-proven): grid (NMOD, chunks). Block = module m x 2048
// batches; 8 tiles of 256 rows, double-buffered TMA. Box inner coordinate
// 16B-aligned: c0 = m*50 - 2*(m&1); genes at word offset 2*(m&1).
// ---------------------------------------------------------------------------
__global__ __launch_bounds__(T1, 2)
void flux_mod_tma(const __grid_constant__ CUtensorMap tmap,
                  const float* __restrict__ W1,
                  const float* __restrict__ W2,
                  const float* __restrict__ b2,
                  int chunk0)
{
    __shared__ __align__(16) float W1s[NGENE * NHID];
    __shared__ float W2s[NHID];
    __shared__ float b2s_;
    __shared__ __align__(8) uint64_t barmem[2];
    extern __shared__ __align__(16) float sx[];     // [2][TROW*XS]

    const int m    = blockIdx.x;
    const int ch   = chunk0 + blockIdx.y;
    const int t    = threadIdx.x;
    const int warp = t >> 5;
    const int lane = t & 31;

    const uint32_t sxa  = (uint32_t)__cvta_generic_to_shared(sx);
    const uint32_t bara = (uint32_t)__cvta_generic_to_shared(barmem);

    for (int i = t; i < NGENE * NHID; i += T1)
        W1s[i] = W1[(size_t)m * (NGENE * NHID) + i];
    if (t < NHID) W2s[t] = W2[m * NHID + t];
    if (t == 0) {
        b2s_ = b2[m];
        mbar_init(bara, 1);
        mbar_init(bara + 8, 1);
    }
    __syncthreads();

    const int ofs = 2 * (m & 1);                    // gene word offset in row
    const int c0  = m * NGENE - ofs;                // 16B-aligned inner coord
    const int bbase = ch * (NT * TROW);

    if (t == 0) {                                   // stage tile 0 -> buf 0
        mbar_expect_tx(bara, TILE_BYTES);
        tma_2d(sxa, &tmap, c0, bbase, bara);
    }

    #pragma unroll 1
    for (int s = 0; s < NT; s++) {
        const int buf = s & 1;
        if (t == 0 && s + 1 < NT) {                 // prefetch tile s+1
            const int nbuf = (s + 1) & 1;
            mbar_expect_tx(bara + 8u * nbuf, TILE_BYTES);
            tma_2d(sxa + (uint32_t)nbuf * TILE_BYTES, &tmap, c0,
                   bbase + (s + 1) * TROW, bara + 8u * nbuf);
        }
        mbar_wait(bara + 8u * buf, (s >> 1) & 1);   // tile s data ready

        const float* __restrict__ row =
            sx + buf * (TROW * XS) + (warp * 32 + lane) * XS + ofs;
        float mv = module_mlp(row, W1s, W2s, b2s_);

        const size_t b = (size_t)bbase + s * TROW + warp * 32 + lane;
        g_mT[(size_t)m * BATCH + b] = mv;           // coalesced

        __syncthreads();   // everyone done with buf before it is re-staged
    }
}

// ---------------------------------------------------------------------------
// Kernel 1 fallback (cp.async) — only if TMA encode unavailable.
// ---------------------------------------------------------------------------
__global__ __launch_bounds__(T1F, 1)
void flux_mod_fallback(const float* __restrict__ x,
                       const float* __restrict__ W1,
                       const float* __restrict__ W2,
                       const float* __restrict__ b2)
{
    __shared__ __align__(16) float W1s[NGENE * NHID];
    __shared__ float W2s[NHID];
    __shared__ float b2s_;
    extern __shared__ float sxf[];   // [8][2][SUBB*FXS]

    const int m     = blockIdx.x;
    const int chunk = blockIdx.y;
    const int t     = threadIdx.x;
    const int warp  = t >> 5;
    const int lane  = t & 31;

    for (int i = t; i < NGENE * NHID; i += T1F)
        W1s[i] = W1[(size_t)m * (NGENE * NHID) + i];
    if (t < NHID) W2s[t] = W2[m * NHID + t];
    if (t == 0)   b2s_ = b2[m];
    __syncthreads();

    const size_t wbase = (size_t)chunk * BLKB + (size_t)warp * WBATCH;
    const float* xw = x + wbase * (NMOD * NGENE) + (size_t)m * NGENE;
    float* wbuf = sxf + warp * (2 * SUBB * FXS);
    const uint32_t sdst = (uint32_t)__cvta_generic_to_shared(wbuf);

    auto stage = [&](int buf, int s) {
        const float* src0 = xw + (size_t)s * SUBB * (NMOD * NGENE);
        const uint32_t dst0 = sdst + (uint32_t)buf * (SUBB * FXS * 4);
        #pragma unroll
        for (int i = 0; i < 50; i++) {
            const int c = lane + i * 32;
            const int r = (c * 5243) >> 17;
            const int j = c - r * 25;
            cp_async8(dst0 + (uint32_t)(r * FXS + 2 * j) * 4,
                      src0 + (size_t)r * (NMOD * NGENE) + 2 * j);
        }
        cp_commit();
    };

    stage(0, 0);
    #pragma unroll 1
    for (int s = 0; s < NSUB; s++) {
        if (s + 1 < NSUB) { stage((s + 1) & 1, s + 1); cp_wait<1>(); }
        else              { cp_wait<0>(); }
        __syncwarp();

        const float* r0 = wbuf + (s & 1) * (SUBB * FXS) + lane * FXS;
        float mv0 = module_mlp(r0, W1s, W2s, b2s_);
        float mv1 = module_mlp(r0 + 32 * FXS, W1s, W2s, b2s_);

        const size_t b = wbase + (size_t)s * SUBB + lane;
        g_mT[(size_t)m * BATCH + b]      = mv0;
        g_mT[(size_t)m * BATCH + b + 32] = mv1;
        __syncwarp();
    }
}

// ---------------------------------------------------------------------------
// Kernel 2 (T2=512, 2 blocks/SM -> 32 warps/SM): out_m transpose emission +
// out_c = m @ cmMat^T with coalesced out_c emission via smem staging.
// Per-element arithmetic identical to the R5/R9 version (same k order).
// ---------------------------------------------------------------------------
__global__ __launch_bounds__(T2, 2)
void flux_comp_kernel(const float* __restrict__ cmMat,
                      float* __restrict__ out_m,
                      float* __restrict__ out_c)
{
    extern __shared__ float sh[];
    float* scm = sh;                        // [CPAD][256]
    float* sm  = sh + CPAD * NMOD;          // [256][MS2]

    const int t  = threadIdx.x;
    const int bb = blockIdx.x;
    const size_t bbase = (size_t)bb * BT2;

    for (int i = t; i < NCOMP * NMOD; i += T2) scm[i] = cmMat[i];
    for (int i = t; i < (CPAD - NCOMP) * NMOD; i += T2) scm[NCOMP * NMOD + i] = 0.f;

    for (int i = t; i < BT2 * NMOD; i += T2) {
        int k = i >> 5, b = i & 31;
        sm[k * MS2 + b] = g_mT[(size_t)k * BATCH + bbase + b];   // coalesced
    }
    __syncthreads();

    // out_m: conflict-free smem read, coalesced global write
    for (int i = t; i < BT2 * NMOD; i += T2) {
        int b = i >> 8, k = i & 255;
        out_m[(bbase + b) * NMOD + k] = sm[k * MS2 + b];
    }

    // dot: lane = batch b0, warp-uniform comp group cg (16 groups, 5 comps ea.)
    const int b0 = t & 31;
    const int cg = t >> 5;                  // 0..15
    float acc[5];
    #pragma unroll
    for (int i = 0; i < 5; i++) acc[i] = 0.f;

    for (int k = 0; k < NMOD; k += 4) {
        float mv0 = sm[(k + 0) * MS2 + b0];
        float mv1 = sm[(k + 1) * MS2 + b0];
        float mv2 = sm[(k + 2) * MS2 + b0];
        float mv3 = sm[(k + 3) * MS2 + b0];
        #pragma unroll
        for (int idx = 0; idx < 5; idx++) {
            const int cc = cg + idx * 16;
            if (cc < NCOMP) {               // warp-uniform predicate
                float4 cv = *reinterpret_cast<const float4*>(scm + cc * NMOD + k);
                acc[idx] = fmaf(mv0, cv.x,
                           fmaf(mv1, cv.y,
                           fmaf(mv2, cv.z,
                           fmaf(mv3, cv.w, acc[idx]))));
            }
        }
    }

    __syncthreads();                        // all sm reads done
    float* sc = sm;                         // reuse m-tile space: [32][CS2]
    #pragma unroll
    for (int idx = 0; idx < 5; idx++) {
        const int cc = cg + idx * 16;
        if (cc < NCOMP) sc[b0 * CS2 + cc] = acc[idx];
    }
    __syncthreads();

    // out_c: coalesced emission
    for (int i = t; i < BT2 * NCOMP; i += T2) {
        int b = i / NCOMP, c = i - b * NCOMP;
        out_c[(bbase + b) * NCOMP + c] = sc[b * CS2 + c];
    }
}

// ---------------------------------------------------------------------------
// TMA path launch order: [k1 ch0-2, k1 ch3-5, k1 ch6-7, k2] (period 4 -> ncu
// -s 5 -c 1 lands on a k1 instance).
// ---------------------------------------------------------------------------
extern "C" void kernel_launch(void* const* d_in, const int* in_sizes, int n_in,
                              void* d_out, int out_size)
{
    const float* x     = (const float*)d_in[0];  // [B, M*G]
    const float* W1    = (const float*)d_in[1];  // [M, G, H]
    const float* W2    = (const float*)d_in[2];  // [M, H]
    const float* b2    = (const float*)d_in[3];  // [M]
    const float* cmMat = (const float*)d_in[4];  // [C, M]
    (void)in_sizes; (void)n_in; (void)out_size;

    float* out   = (float*)d_out;
    float* out_m = out;                            // [B, M]
    float* out_c = out + (size_t)BATCH * NMOD;     // [B, C]

    typedef CUresult (*EncodeFn)(CUtensorMap*, CUtensorMapDataType, cuuint32_t,
        void*, const cuuint64_t*, const cuuint64_t*, const cuuint32_t*,
        const cuuint32_t*, CUtensorMapInterleave, CUtensorMapSwizzle,
        CUtensorMapL2promotion, CUtensorMapFloatOOBfill);

    void* fn = nullptr;
    cudaDriverEntryPointQueryResult qres = cudaDriverEntryPointSuccess;
    bool use_tma =
        (cudaGetDriverEntryPoint("cuTensorMapEncodeTiled", &fn,
                                 cudaEnableDefault, &qres) == cudaSuccess)
        && fn != nullptr && qres == cudaDriverEntryPointSuccess;

    CUtensorMap tmap;
    if (use_tma) {
        cuuint64_t dims[2]    = {(cuuint64_t)(NMOD * NGENE), (cuuint64_t)BATCH};
        cuuint64_t strides[1] = {(cuuint64_t)(NMOD * NGENE) * sizeof(float)};
        cuuint32_t box[2]     = {XS, TROW};        // 52 x 256 (208B rows)
        cuuint32_t estr[2]    = {1, 1};
        use_tma = ((EncodeFn)fn)(&tmap, CU_TENSOR_MAP_DATA_TYPE_FLOAT32, 2,
                      (void*)x, dims, strides, box, estr,
                      CU_TENSOR_MAP_INTERLEAVE_NONE, CU_TENSOR_MAP_SWIZZLE_NONE,
                      CU_TENSOR_MAP_L2_PROMOTION_L2_128B,
                      CU_TENSOR_MAP_FLOAT_OOB_FILL_NONE) == CUDA_SUCCESS;
    }

    const int smem2 = (CPAD * NMOD + NMOD * MS2) * sizeof(float);   // 107520
    cudaFuncSetAttribute(flux_comp_kernel,
                         cudaFuncAttributeMaxDynamicSharedMemorySize, smem2);

    if (use_tma) {
        const int smem1 = 2 * TILE_BYTES;                          // 106496
        cudaFuncSetAttribute(flux_mod_tma,
                             cudaFuncAttributeMaxDynamicSharedMemorySize, smem1);
        flux_mod_tma<<<dim3(NMOD, 3), T1, smem1>>>(tmap, W1, W2, b2, 0);
        flux_mod_tma<<<dim3(NMOD, 3), T1, smem1>>>(tmap, W1, W2, b2, 3);
        flux_mod_tma<<<dim3(NMOD, 2), T1, smem1>>>(tmap, W1, W2, b2, 6);
    } else {
        const int smem1f = 8 * 2 * SUBB * FXS * sizeof(float);     // 204800
        cudaFuncSetAttribute(flux_mod_fallback,
                             cudaFuncAttributeMaxDynamicSharedMemorySize, smem1f);
        flux_mod_fallback<<<dim3(NMOD, 8), T1F, smem1f>>>(x, W1, W2, b2);
    }

    flux_comp_kernel<<<BATCH / BT2, T2, smem2>>>(cmMat, out_m, out_c);
}

// round 15
// speedup vs baseline: 1.2448x; 1.2448x over previous
#include <cuda_runtime.h>
#include <cuda.h>
#include <math.h>
#include <stdint.h>

// Problem constants (fixed by the dataset)
#define BATCH   16384
#define NMOD    256
#define NGENE   50
#define NHID    8
#define NCOMP   70

// ---------------- Kernel 1 (TMA, scalar, R9-proven) ----------------
#define T1      256          // threads (8 warps)
#define TROW    256          // batch rows per tile (TMA box dim1)
#define XS      52           // floats per smem row = TMA box dim0 (208B = 13*16)
#define NT      8            // tiles per block
#define NCH     8            // grid.y: NCH*NT*TROW == BATCH
#define TILE_BYTES (TROW * XS * 4)   // 53248

// ---------------- Kernel 1 fallback (cp.async, scalar) ----------------
#define T1F      256
#define SUBB     64
#define NSUB     4
#define WBATCH   (SUBB*NSUB)
#define BLKB     (8*WBATCH)   // 2048
#define FXS      50

// ---------------- Kernel 2 (cp.async staged) ----------------
#define BT2     32
#define T2      256
#define CPAD    72
#define MS2     36           // m-tile row stride (144B, 16B-aligned rows)

// Scratch: m transposed [M][B] (kernel1 writes / kernel2 reads coalesced)
__device__ float g_mT[(size_t)NMOD * BATCH];

// ---------------------------------------------------------------------------
// PTX helpers
// ---------------------------------------------------------------------------
__device__ __forceinline__ void mbar_init(uint32_t mbar, uint32_t cnt) {
    asm volatile("mbarrier.init.shared.b64 [%0], %1;" :: "r"(mbar), "r"(cnt) : "memory");
}
__device__ __forceinline__ void mbar_expect_tx(uint32_t mbar, uint32_t bytes) {
    asm volatile("mbarrier.arrive.expect_tx.shared.b64 _, [%0], %1;"
                 :: "r"(mbar), "r"(bytes) : "memory");
}
__device__ __forceinline__ void mbar_wait(uint32_t mbar, uint32_t parity) {
    asm volatile(
        "{\n\t.reg .pred P1;\n\t"
        "W_%=:\n\t"
        "mbarrier.try_wait.parity.acquire.cta.shared::cta.b64 P1, [%0], %1, 0x989680;\n\t"
        "@P1 bra.uni D_%=;\n\t"
        "bra.uni W_%=;\n\t"
        "D_%=:\n\t}"
        :: "r"(mbar), "r"(parity) : "memory");
}
__device__ __forceinline__ void tma_2d(uint32_t dst, const CUtensorMap* tmap,
                                       int c0, int c1, uint32_t mbar) {
    asm volatile(
        "cp.async.bulk.tensor.2d.shared::cta.global.tile.mbarrier::complete_tx::bytes "
        "[%0], [%1, {%2, %3}], [%4];"
        :: "r"(dst), "l"(tmap), "r"(c0), "r"(c1), "r"(mbar) : "memory");
}
__device__ __forceinline__ void cp_async8(uint32_t dst, const float* src) {
    asm volatile("cp.async.ca.shared.global [%0], [%1], 8;\n" :: "r"(dst), "l"(src));
}
__device__ __forceinline__ void cp_async16(uint32_t dst, const float* src) {
    asm volatile("cp.async.cg.shared.global [%0], [%1], 16;\n" :: "r"(dst), "l"(src));
}
__device__ __forceinline__ void cp_commit() {
    asm volatile("cp.async.commit_group;\n" ::: "memory");
}
template <int N>
__device__ __forceinline__ void cp_wait() {
    asm volatile("cp.async.wait_group %0;\n" :: "n"(N) : "memory");
}
__device__ __forceinline__ float rcp_approx(float x) {
    float r; asm("rcp.approx.f32 %0, %1;" : "=f"(r) : "f"(x)); return r;
}

// ---------------------------------------------------------------------------
// Branch-free tanhshrink: x - tanh(x) = x*C(x^2)/B(x^2) (Eigen rational,
// C=B-A exact). Reciprocal via MUFU rcp.approx (2^-22 rel, multiplicative
// only — no cancellation path), saving ~7 fma-pipe ops vs Newton.
// ---------------------------------------------------------------------------
__device__ __forceinline__ float tanhshrink_fast(float x) {
    float xc = fminf(fmaxf(x, -7.90531f), 7.90531f);
    float u  = xc * xc;
    float C  = fmaf(u, 2.76076847742355e-16f, -2.00018790482477e-13f);
    C = fmaf(u, C, 8.60467152213735e-11f);
    C = fmaf(u, C, 1.14703542376332e-06f);
    C = fmaf(u, C, 1.03677482114856e-04f);
    C = fmaf(u, C, 1.63117270356356e-03f);
    C = fmaf(u, C, 6.26625990e-10f);
    float B  = fmaf(u, 1.19825839466702e-06f, 1.18534705686654e-04f);
    B = fmaf(u, B, 2.26843463243900e-03f);
    B = fmaf(u, B, 4.89352518554385e-03f);
    return (x - xc) + xc * C * rcp_approx(B);
}

// ---------------------------------------------------------------------------
// Core math: per-lane 50x8 MLP + tanhshrink, weights broadcast from smem.
// ---------------------------------------------------------------------------
__device__ __forceinline__ float module_mlp(const float* __restrict__ row,
                                            const float* __restrict__ W1s,
                                            const float* __restrict__ W2s,
                                            float b2v)
{
    float h[NHID];
    #pragma unroll
    for (int j = 0; j < NHID; j++) h[j] = 0.f;

    #pragma unroll 5
    for (int gp = 0; gp < NGENE / 2; gp++) {
        const int g = gp * 2;
        float2 a = *reinterpret_cast<const float2*>(row + g);           // LDS.64
        float4 wa = *reinterpret_cast<const float4*>(W1s + g * 8);      // uniform
        float4 wb = *reinterpret_cast<const float4*>(W1s + g * 8 + 4);
        float4 wc = *reinterpret_cast<const float4*>(W1s + g * 8 + 8);
        float4 wd = *reinterpret_cast<const float4*>(W1s + g * 8 + 12);
        h[0] = fmaf(a.x, wa.x, h[0]); h[1] = fmaf(a.x, wa.y, h[1]);
        h[2] = fmaf(a.x, wa.z, h[2]); h[3] = fmaf(a.x, wa.w, h[3]);
        h[4] = fmaf(a.x, wb.x, h[4]); h[5] = fmaf(a.x, wb.y, h[5]);
        h[6] = fmaf(a.x, wb.z, h[6]); h[7] = fmaf(a.x, wb.w, h[7]);
        h[0] = fmaf(a.y, wc.x, h[0]); h[1] = fmaf(a.y, wc.y, h[1]);
        h[2] = fmaf(a.y, wc.z, h[2]); h[3] = fmaf(a.y, wc.w, h[3]);
        h[4] = fmaf(a.y, wd.x, h[4]); h[5] = fmaf(a.y, wd.y, h[5]);
        h[6] = fmaf(a.y, wd.z, h[6]); h[7] = fmaf(a.y, wd.w, h[7]);
    }
    float acc = b2v;
    #pragma unroll
    for (int j = 0; j < NHID; j++)
        acc = fmaf(tanhshrink_fast(h[j]), W2s[j], acc);
    return tanhshrink_fast(acc);
}

// ---------------------------------------------------------------------------
// Kernel 1 (TMA, R9-proven structure): grid (NMOD, NCH). Block = module m x
// 2048 batches; 8 tiles of 256 rows, double-buffered TMA. Box inner coord
// 16B-aligned: c0 = m*50 - 2*(m&1); genes at word offset 2*(m&1).
// ---------------------------------------------------------------------------
__global__ __launch_bounds__(T1, 2)
void flux_mod_tma(const __grid_constant__ CUtensorMap tmap,
                  const float* __restrict__ W1,
                  const float* __restrict__ W2,
                  const float* __restrict__ b2)
{
    __shared__ __align__(16) float W1s[NGENE * NHID];
    __shared__ float W2s[NHID];
    __shared__ float b2s_;
    __shared__ __align__(8) uint64_t barmem[2];
    extern __shared__ __align__(16) float sx[];     // [2][TROW*XS]

    const int m    = blockIdx.x;
    const int ch   = blockIdx.y;
    const int t    = threadIdx.x;
    const int warp = t >> 5;
    const int lane = t & 31;

    const uint32_t sxa  = (uint32_t)__cvta_generic_to_shared(sx);
    const uint32_t bara = (uint32_t)__cvta_generic_to_shared(barmem);

    for (int i = t; i < NGENE * NHID; i += T1)
        W1s[i] = W1[(size_t)m * (NGENE * NHID) + i];
    if (t < NHID) W2s[t] = W2[m * NHID + t];
    if (t == 0) {
        b2s_ = b2[m];
        mbar_init(bara, 1);
        mbar_init(bara + 8, 1);
    }
    __syncthreads();

    const int ofs = 2 * (m & 1);                    // gene word offset in row
    const int c0  = m * NGENE - ofs;                // 16B-aligned inner coord
    const int bbase = ch * (NT * TROW);

    if (t == 0) {                                   // stage tile 0 -> buf 0
        mbar_expect_tx(bara, TILE_BYTES);
        tma_2d(sxa, &tmap, c0, bbase, bara);
    }

    #pragma unroll 1
    for (int s = 0; s < NT; s++) {
        const int buf = s & 1;
        if (t == 0 && s + 1 < NT) {                 // prefetch tile s+1
            const int nbuf = (s + 1) & 1;
            mbar_expect_tx(bara + 8u * nbuf, TILE_BYTES);
            tma_2d(sxa + (uint32_t)nbuf * TILE_BYTES, &tmap, c0,
                   bbase + (s + 1) * TROW, bara + 8u * nbuf);
        }
        mbar_wait(bara + 8u * buf, (s >> 1) & 1);   // tile s data ready

        const float* __restrict__ row =
            sx + buf * (TROW * XS) + (warp * 32 + lane) * XS + ofs;
        float mv = module_mlp(row, W1s, W2s, b2s_);

        const size_t b = (size_t)bbase + s * TROW + warp * 32 + lane;
        g_mT[(size_t)m * BATCH + b] = mv;           // coalesced

        __syncthreads();   // everyone done with buf before it is re-staged
    }
}

// ---------------------------------------------------------------------------
// Kernel 1 fallback (cp.async) — only if TMA encode unavailable.
// ---------------------------------------------------------------------------
__global__ __launch_bounds__(T1F, 1)
void flux_mod_fallback(const float* __restrict__ x,
                       const float* __restrict__ W1,
                       const float* __restrict__ W2,
                       const float* __restrict__ b2)
{
    __shared__ __align__(16) float W1s[NGENE * NHID];
    __shared__ float W2s[NHID];
    __shared__ float b2s_;
    extern __shared__ float sxf[];   // [8][2][SUBB*FXS]

    const int m     = blockIdx.x;
    const int chunk = blockIdx.y;
    const int t     = threadIdx.x;
    const int warp  = t >> 5;
    const int lane  = t & 31;

    for (int i = t; i < NGENE * NHID; i += T1F)
        W1s[i] = W1[(size_t)m * (NGENE * NHID) + i];
    if (t < NHID) W2s[t] = W2[m * NHID + t];
    if (t == 0)   b2s_ = b2[m];
    __syncthreads();

    const size_t wbase = (size_t)chunk * BLKB + (size_t)warp * WBATCH;
    const float* xw = x + wbase * (NMOD * NGENE) + (size_t)m * NGENE;
    float* wbuf = sxf + warp * (2 * SUBB * FXS);
    const uint32_t sdst = (uint32_t)__cvta_generic_to_shared(wbuf);

    auto stage = [&](int buf, int s) {
        const float* src0 = xw + (size_t)s * SUBB * (NMOD * NGENE);
        const uint32_t dst0 = sdst + (uint32_t)buf * (SUBB * FXS * 4);
        #pragma unroll
        for (int i = 0; i < 50; i++) {
            const int c = lane + i * 32;
            const int r = (c * 5243) >> 17;
            const int j = c - r * 25;
            cp_async8(dst0 + (uint32_t)(r * FXS + 2 * j) * 4,
                      src0 + (size_t)r * (NMOD * NGENE) + 2 * j);
        }
        cp_commit();
    };

    stage(0, 0);
    #pragma unroll 1
    for (int s = 0; s < NSUB; s++) {
        if (s + 1 < NSUB) { stage((s + 1) & 1, s + 1); cp_wait<1>(); }
        else              { cp_wait<0>(); }
        __syncwarp();

        const float* r0 = wbuf + (s & 1) * (SUBB * FXS) + lane * FXS;
        float mv0 = module_mlp(r0, W1s, W2s, b2s_);
        float mv1 = module_mlp(r0 + 32 * FXS, W1s, W2s, b2s_);

        const size_t b = wbase + (size_t)s * SUBB + lane;
        g_mT[(size_t)m * BATCH + b]      = mv0;
        g_mT[(size_t)m * BATCH + b + 32] = mv1;
        __syncwarp();
    }
}

// ---------------------------------------------------------------------------
// Kernel 2 (cp.async staged): out_m transpose emission + out_c = m @ cmMat^T.
// Staging of cmMat (71680B) and the m-tile (rows of 128B, stride 144B) goes
// through 16B cp.async -> deep MLP, no register round-trip. Compute identical
// to the R9 version (same k order -> same numerics).
// ---------------------------------------------------------------------------
__global__ __launch_bounds__(T2, 2)
void flux_comp_kernel(const float* __restrict__ cmMat,
                      float* __restrict__ out_m,
                      float* __restrict__ out_c)
{
    extern __shared__ __align__(16) float sh[];
    float* scm = sh;                        // [CPAD][256] contiguous
    float* sm  = sh + CPAD * NMOD;          // [256][MS2]  (MS2=36 words)

    const int t  = threadIdx.x;
    const int bb = blockIdx.x;
    const size_t bbase = (size_t)bb * BT2;

    const uint32_t scma = (uint32_t)__cvta_generic_to_shared(scm);
    const uint32_t sma  = (uint32_t)__cvta_generic_to_shared(sm);

    // cmMat: 17920 floats = 4480 x 16B chunks, linear
    #pragma unroll 4
    for (int i = t; i < (NCOMP * NMOD) / 4; i += T2)
        cp_async16(scma + (uint32_t)i * 16, cmMat + i * 4);
    // zero-pad rows [70,72)
    for (int i = t; i < (CPAD - NCOMP) * NMOD; i += T2)
        scm[NCOMP * NMOD + i] = 0.f;
    // m-tile: 256 rows x 128B; 8 x 16B chunks per row, 16B-aligned dst
    #pragma unroll 8
    for (int i = t; i < NMOD * 8; i += T2) {
        const int k = i >> 3, c = i & 7;
        cp_async16(sma + (uint32_t)(k * MS2 + c * 4) * 4,
                   &g_mT[(size_t)k * BATCH + bbase] + c * 4);
    }
    cp_commit();
    cp_wait<0>();
    __syncthreads();

    // out_m: smem read (stride MS2=36 -> 4-way conflict, minor), coalesced write
    for (int i = t; i < BT2 * NMOD; i += T2) {
        int b = i >> 8, k = i & 255;
        out_m[(bbase + b) * NMOD + k] = sm[k * MS2 + b];
    }

    // dot: lane = batch b0, warp-uniform comp group cg (8 groups, 9 comps ea.)
    const int b0 = t & 31;
    const int cg = t >> 5;
    float acc[9];
    #pragma unroll
    for (int i = 0; i < 9; i++) acc[i] = 0.f;

    for (int k = 0; k < NMOD; k += 4) {
        float mv0 = sm[(k + 0) * MS2 + b0];
        float mv1 = sm[(k + 1) * MS2 + b0];
        float mv2 = sm[(k + 2) * MS2 + b0];
        float mv3 = sm[(k + 3) * MS2 + b0];
        #pragma unroll
        for (int idx = 0; idx < 9; idx++) {
            const int cc = cg + idx * 8;
            float4 cv = *reinterpret_cast<const float4*>(scm + cc * NMOD + k);
            acc[idx] = fmaf(mv0, cv.x,
                       fmaf(mv1, cv.y,
                       fmaf(mv2, cv.z,
                       fmaf(mv3, cv.w, acc[idx]))));
        }
    }

    const size_t gb = bbase + b0;
    #pragma unroll
    for (int idx = 0; idx < 9; idx++) {
        const int cc = cg + idx * 8;
        if (cc < NCOMP)
            out_c[gb * NCOMP + cc] = acc[idx];
    }
}

// ---------------------------------------------------------------------------
extern "C" void kernel_launch(void* const* d_in, const int* in_sizes, int n_in,
                              void* d_out, int out_size)
{
    const float* x     = (const float*)d_in[0];  // [B, M*G]
    const float* W1    = (const float*)d_in[1];  // [M, G, H]
    const float* W2    = (const float*)d_in[2];  // [M, H]
    const float* b2    = (const float*)d_in[3];  // [M]
    const float* cmMat = (const float*)d_in[4];  // [C, M]
    (void)in_sizes; (void)n_in; (void)out_size;

    float* out   = (float*)d_out;
    float* out_m = out;                            // [B, M]
    float* out_c = out + (size_t)BATCH * NMOD;     // [B, C]

    typedef CUresult (*EncodeFn)(CUtensorMap*, CUtensorMapDataType, cuuint32_t,
        void*, const cuuint64_t*, const cuuint64_t*, const cuuint32_t*,
        const cuuint32_t*, CUtensorMapInterleave, CUtensorMapSwizzle,
        CUtensorMapL2promotion, CUtensorMapFloatOOBfill);

    void* fn = nullptr;
    cudaDriverEntryPointQueryResult qres = cudaDriverEntryPointSuccess;
    bool use_tma =
        (cudaGetDriverEntryPoint("cuTensorMapEncodeTiled", &fn,
                                 cudaEnableDefault, &qres) == cudaSuccess)
        && fn != nullptr && qres == cudaDriverEntryPointSuccess;

    CUtensorMap tmap;
    if (use_tma) {
        cuuint64_t dims[2]    = {(cuuint64_t)(NMOD * NGENE), (cuuint64_t)BATCH};
        cuuint64_t strides[1] = {(cuuint64_t)(NMOD * NGENE) * sizeof(float)};
        cuuint32_t box[2]     = {XS, TROW};        // 52 x 256 (208B rows)
        cuuint32_t estr[2]    = {1, 1};
        use_tma = ((EncodeFn)fn)(&tmap, CU_TENSOR_MAP_DATA_TYPE_FLOAT32, 2,
                      (void*)x, dims, strides, box, estr,
                      CU_TENSOR_MAP_INTERLEAVE_NONE, CU_TENSOR_MAP_SWIZZLE_NONE,
                      CU_TENSOR_MAP_L2_PROMOTION_L2_128B,
                      CU_TENSOR_MAP_FLOAT_OOB_FILL_NONE) == CUDA_SUCCESS;
    }

    const int smem2 = (CPAD * NMOD + NMOD * MS2) * sizeof(float);   // 110592
    cudaFuncSetAttribute(flux_comp_kernel,
                         cudaFuncAttributeMaxDynamicSharedMemorySize, smem2);

    if (use_tma) {
        const int smem1 = 2 * TILE_BYTES;                          // 106496
        cudaFuncSetAttribute(flux_mod_tma,
                             cudaFuncAttributeMaxDynamicSharedMemorySize, smem1);
        flux_mod_tma<<<dim3(NMOD, NCH), T1, smem1>>>(tmap, W1, W2, b2);
    } else {
        const int smem1f = 8 * 2 * SUBB * FXS * sizeof(float);     // 204800
        cudaFuncSetAttribute(flux_mod_fallback,
                             cudaFuncAttributeMaxDynamicSharedMemorySize, smem1f);
        flux_mod_fallback<<<dim3(NMOD, 8), T1F, smem1f>>>(x, W1, W2, b2);
    }

    flux_comp_kernel<<<BATCH / BT2, T2, smem2>>>(cmMat, out_m, out_c);
}